// round 4
// baseline (speedup 1.0000x reference)
#include <cuda_runtime.h>
#include <cuda_bf16.h>
#include <math.h>
#include <stdint.h>

// Problem constants
#define LAYERS 4
#define D_     128
#define N_     2048
#define TWON   4096
#define INV_T  5.0f
#define EPS    1e-12f
#define C_EX2  7.21347520444481703076f   // (1/T) * log2(e)

#define NCHUNK 32          // 4096 / 128 cols per chunk
#define CHUNK  128
#define SROWB  272         // smem row stride bytes (128 bf16 + 16B pad)
#define TILEB  (128 * SROWB)

// Scratch
__device__ __align__(256) __nv_bfloat16 g_zb[LAYERS * TWON * D_];
__device__ float g_lp[LAYERS * TWON];

// ---------------------------------------------------------------------------
__device__ __forceinline__ uint32_t smem_u32(const void* p) {
    uint32_t a;
    asm("{ .reg .u64 t; cvta.to.shared.u64 t, %1; cvt.u32.u64 %0, t; }" : "=r"(a) : "l"(p));
    return a;
}
__device__ __forceinline__ float ex2f(float x) {
    float r; asm("ex2.approx.ftz.f32 %0, %1;" : "=f"(r) : "f"(x)); return r;
}
#define CP_ASYNC16(dst, src) \
    asm volatile("cp.async.cg.shared.global [%0], [%1], 16;" :: "r"(dst), "l"(src))
#define CP_COMMIT() asm volatile("cp.async.commit_group;" ::: "memory")
#define CP_WAIT(n)  asm volatile("cp.async.wait_group %0;" :: "n"(n) : "memory")

__device__ __forceinline__ void ldsm4(uint32_t* r, uint32_t addr) {
    asm volatile("ldmatrix.sync.aligned.m8n8.x4.shared.b16 {%0,%1,%2,%3}, [%4];"
                 : "=r"(r[0]), "=r"(r[1]), "=r"(r[2]), "=r"(r[3]) : "r"(addr));
}
__device__ __forceinline__ void mma_bf16(float* c, const uint32_t* a, const uint32_t* b) {
    asm volatile(
        "mma.sync.aligned.m16n8k16.row.col.f32.bf16.bf16.f32 "
        "{%0,%1,%2,%3}, {%4,%5,%6,%7}, {%8,%9}, {%0,%1,%2,%3};"
        : "+f"(c[0]), "+f"(c[1]), "+f"(c[2]), "+f"(c[3])
        : "r"(a[0]), "r"(a[1]), "r"(a[2]), "r"(a[3]), "r"(b[0]), "r"(b[1]));
}

// ---------------------------------------------------------------------------
// Kernel 1: L2-normalize -> bf16.  One warp per TWO rows (MLP=2).
// ---------------------------------------------------------------------------
__global__ void norm_bf16_kernel(const float* __restrict__ emb_i,
                                 const float* __restrict__ emb_j) {
    int gw   = (blockIdx.x * blockDim.x + threadIdx.x) >> 5;
    int lane = threadIdx.x & 31;
    int base = gw * 2;
    if (base >= LAYERS * TWON) return;

    int layer = base >> 12;
    int row0  = base & (TWON - 1);

    const float* s0 = (row0 < N_)
        ? (emb_i + ((size_t)layer * N_ + row0) * D_)
        : (emb_j + ((size_t)layer * N_ + (row0 - N_)) * D_);
    int row1 = row0 + 1;
    const float* s1 = (row1 < N_)
        ? (emb_i + ((size_t)layer * N_ + row1) * D_)
        : (emb_j + ((size_t)layer * N_ + (row1 - N_)) * D_);

    float4 v0 = ((const float4*)s0)[lane];
    float4 v1 = ((const float4*)s1)[lane];
    float a = v0.x * v0.x + v0.y * v0.y + v0.z * v0.z + v0.w * v0.w;
    float b = v1.x * v1.x + v1.y * v1.y + v1.z * v1.z + v1.w * v1.w;
    #pragma unroll
    for (int o = 16; o > 0; o >>= 1) {
        a += __shfl_xor_sync(0xffffffffu, a, o);
        b += __shfl_xor_sync(0xffffffffu, b, o);
    }
    float ia = 1.0f / fmaxf(sqrtf(a), EPS);
    float ib = 1.0f / fmaxf(sqrtf(b), EPS);

    uint2 u0, u1;
    u0.x = (uint32_t)__bfloat16_as_ushort(__float2bfloat16(v0.x * ia))
         | ((uint32_t)__bfloat16_as_ushort(__float2bfloat16(v0.y * ia)) << 16);
    u0.y = (uint32_t)__bfloat16_as_ushort(__float2bfloat16(v0.z * ia))
         | ((uint32_t)__bfloat16_as_ushort(__float2bfloat16(v0.w * ia)) << 16);
    u1.x = (uint32_t)__bfloat16_as_ushort(__float2bfloat16(v1.x * ib))
         | ((uint32_t)__bfloat16_as_ushort(__float2bfloat16(v1.y * ib)) << 16);
    u1.y = (uint32_t)__bfloat16_as_ushort(__float2bfloat16(v1.z * ib))
         | ((uint32_t)__bfloat16_as_ushort(__float2bfloat16(v1.w * ib)) << 16);
    ((uint2*)(g_zb + ((size_t)layer * TWON + row0) * D_))[lane] = u0;
    ((uint2*)(g_zb + ((size_t)layer * TWON + row1) * D_))[lane] = u1;
}

// ---------------------------------------------------------------------------
// Kernel 2: fused Gram + exp + row reduction (mma.sync bf16).
// Grid = LAYERS*32; block = 256 (8 warps, 4x2 warp grid: m_w=32, n_w=64).
// A fragments register-resident (loaded once). B streamed in 128-col chunks,
// double-buffered cp.async. SMSP warp pairs phase-staggered: warps with
// wid>>2==1 run the exp epilogue of chunk ct-1 BEFORE the MMA of chunk ct,
// overlapping MUFU with the partner warp's HMMA.
// ---------------------------------------------------------------------------
extern __shared__ char dsm[];

__device__ __forceinline__ void load_tile(const __nv_bfloat16* Z, int rowBase,
                                          uint32_t base, int tid) {
    #pragma unroll
    for (int i = 0; i < 8; ++i) {
        int idx = i * 256 + tid;
        int r = idx >> 4, sc = idx & 15;
        const char* src = (const char*)(Z + (size_t)(rowBase + r) * D_) + sc * 16;
        CP_ASYNC16(base + r * SROWB + sc * 16, src);
    }
}

__device__ __forceinline__ void do_epilogue(float (&acc)[2][8][4], int ct, int tile,
                                            int rowT, int colTbase,
                                            float* dsum, float* sdg, float* sps) {
    int cb = ct * CHUNK;
    bool chk = (ct == tile) || (ct == (tile ^ (N_ / CHUNK)));
    if (chk) {
        #pragma unroll
        for (int mt = 0; mt < 2; ++mt)
            #pragma unroll
            for (int nt = 0; nt < 8; ++nt)
                #pragma unroll
                for (int ci = 0; ci < 4; ++ci) {
                    float s = acc[mt][nt][ci];
                    int ri = mt * 2 + (ci >> 1);
                    int grow = rowT + mt * 16 + (ci >> 1) * 8;
                    int gcol = cb + colTbase + nt * 8 + (ci & 1);
                    dsum[ri] += ex2f(s * C_EX2);
                    if (gcol == grow)        sdg[ri] = s;
                    if (gcol == (grow ^ N_)) sps[ri] = s;
                    acc[mt][nt][ci] = 0.f;
                }
    } else {
        #pragma unroll
        for (int mt = 0; mt < 2; ++mt)
            #pragma unroll
            for (int nt = 0; nt < 8; ++nt)
                #pragma unroll
                for (int ci = 0; ci < 4; ++ci) {
                    float s = acc[mt][nt][ci];
                    dsum[mt * 2 + (ci >> 1)] += ex2f(s * C_EX2);
                    acc[mt][nt][ci] = 0.f;
                }
    }
}

__global__ void __launch_bounds__(256, 1) sim_mma_kernel() {
    __shared__ float red_d[2][128];
    __shared__ float red_g[2][128];
    __shared__ float red_p[2][128];

    int tid  = threadIdx.x;
    int wid  = tid >> 5;
    int lane = tid & 31;
    int warpRow = wid & 3;      // 4 row slices of 32
    int warpCol = wid >> 2;     // 2 col slices of 64; also the stagger flag
    int stag    = warpCol;      // wid and wid+4 share an SMSP -> differ in stag

    int layer   = blockIdx.x >> 5;
    int tile    = blockIdx.x & 31;
    int rowBase = tile * CHUNK;
    const __nv_bfloat16* Z = g_zb + (size_t)layer * TWON * D_;

    uint32_t sb = (smem_u32(dsm) + 1023) & ~1023u;
    uint32_t aBase = sb;
    uint32_t bBase[2] = { sb + TILEB, sb + 2 * TILEB };

    // Prologue: A tile (group0) then B chunk 0 (group1)
    load_tile(Z, rowBase, aBase, tid);
    CP_COMMIT();
    load_tile(Z, 0, bBase[0], tid);
    CP_COMMIT();

    uint32_t laneA = (uint32_t)((lane & 7) * SROWB + ((lane >> 3) & 1) * (8 * SROWB)
                                + ((lane >> 4) & 1) * 16);
    uint32_t laneB = (uint32_t)((lane & 7) * SROWB + ((lane >> 3) & 1) * 16
                                + ((lane >> 4) & 1) * (8 * SROWB));
    uint32_t aAddr = aBase + (uint32_t)(warpRow * 32 * SROWB) + laneA;

    CP_WAIT(1);                 // A done
    __syncthreads();

    // A fragments -> registers (64 regs), reused across all 32 chunks
    uint32_t aF[2][8][4];
    #pragma unroll
    for (int mt = 0; mt < 2; ++mt)
        #pragma unroll
        for (int kt = 0; kt < 8; ++kt)
            ldsm4(aF[mt][kt], aAddr + (uint32_t)(mt * 16 * SROWB + kt * 32));

    float acc[2][8][4];
    #pragma unroll
    for (int mt = 0; mt < 2; ++mt)
        #pragma unroll
        for (int nt = 0; nt < 8; ++nt)
            #pragma unroll
            for (int ci = 0; ci < 4; ++ci) acc[mt][nt][ci] = 0.f;

    float dsum[4], sdg[4], sps[4];
    #pragma unroll
    for (int i = 0; i < 4; ++i) { dsum[i] = 0.f; sdg[i] = 0.f; sps[i] = 0.f; }

    int rowT     = rowBase + warpRow * 32 + (lane >> 2);  // + mt*16 + 8*(ci>>1)
    int colTbase = warpCol * 64 + (lane & 3) * 2;         // + nt*8 + (ci&1) + cb

    for (int ct = 0; ct < NCHUNK; ++ct) {
        if (ct + 1 < NCHUNK) {
            load_tile(Z, (ct + 1) * CHUNK, bBase[(ct + 1) & 1], tid);
            CP_COMMIT();
            CP_WAIT(1);
        } else {
            CP_WAIT(0);
        }
        __syncthreads();       // B(ct) ready, buffers published

        if (stag && ct > 0)
            do_epilogue(acc, ct - 1, tile, rowT, colTbase, dsum, sdg, sps);

        uint32_t bA = bBase[ct & 1] + (uint32_t)(warpCol * 64 * SROWB) + laneB;
        #pragma unroll
        for (int kt = 0; kt < 8; ++kt) {
            uint32_t bF[8][2];
            #pragma unroll
            for (int np = 0; np < 4; ++np) {
                uint32_t t[4];
                ldsm4(t, bA + (uint32_t)(np * 16 * SROWB + kt * 32));
                bF[2 * np][0] = t[0];     bF[2 * np][1] = t[1];
                bF[2 * np + 1][0] = t[2]; bF[2 * np + 1][1] = t[3];
            }
            #pragma unroll
            for (int mt = 0; mt < 2; ++mt)
                #pragma unroll
                for (int nt = 0; nt < 8; ++nt)
                    mma_bf16(acc[mt][nt], aF[mt][kt], bF[nt]);
        }

        if (!stag)
            do_epilogue(acc, ct, tile, rowT, colTbase, dsum, sdg, sps);

        __syncthreads();       // all reads of bBase[ct&1] done before overwrite
    }
    if (stag)
        do_epilogue(acc, NCHUNK - 1, tile, rowT, colTbase, dsum, sdg, sps);

    // Reduce across lane&3 (4 lanes covering col groups)
    #pragma unroll
    for (int ri = 0; ri < 4; ++ri) {
        #pragma unroll
        for (int o = 1; o <= 2; o <<= 1) {
            dsum[ri] += __shfl_xor_sync(0xffffffffu, dsum[ri], o);
            sdg[ri]  += __shfl_xor_sync(0xffffffffu, sdg[ri], o);
            sps[ri]  += __shfl_xor_sync(0xffffffffu, sps[ri], o);
        }
    }
    if ((lane & 3) == 0) {
        #pragma unroll
        for (int ri = 0; ri < 4; ++ri) {
            int mt = ri >> 1, h = ri & 1;
            int rloc = warpRow * 32 + mt * 16 + h * 8 + (lane >> 2);
            red_d[warpCol][rloc] = dsum[ri];
            red_g[warpCol][rloc] = sdg[ri];
            red_p[warpCol][rloc] = sps[ri];
        }
    }
    __syncthreads();

    if (tid < 128) {
        float d  = red_d[0][tid] + red_d[1][tid];
        float sg = red_g[0][tid] + red_g[1][tid];
        float sp = red_p[0][tid] + red_p[1][tid];
        float denom = d - ex2f(sg * C_EX2);   // exclude diagonal
        g_lp[layer * TWON + rowBase + tid] = logf(denom) - sp * INV_T;
    }
}

// ---------------------------------------------------------------------------
// Kernel 3: deterministic final reduction with joint_valid mask.
// ---------------------------------------------------------------------------
__global__ void finalize_kernel(const float* __restrict__ joint_valid,
                                float* __restrict__ out) {
    __shared__ float s1[256];
    __shared__ float s2[256];
    int tid = threadIdx.x;

    float total = 0.f;
    for (int idx = tid; idx < LAYERS * TWON; idx += 256) {
        int row = idx & (TWON - 1);
        total += g_lp[idx] * joint_valid[row & (N_ - 1)];
    }
    float an = 0.f;
    for (int idx = tid; idx < N_; idx += 256) an += joint_valid[idx];

    s1[tid] = total;
    s2[tid] = an;
    __syncthreads();
    for (int s = 128; s > 0; s >>= 1) {
        if (tid < s) { s1[tid] += s1[tid + s]; s2[tid] += s2[tid + s]; }
        __syncthreads();
    }
    if (tid == 0) out[0] = s1[0] / (2.0f * s2[0]);
}

// ---------------------------------------------------------------------------
extern "C" void kernel_launch(void* const* d_in, const int* in_sizes, int n_in,
                              void* d_out, int out_size) {
    const float* emb_i       = (const float*)d_in[0];
    const float* emb_j       = (const float*)d_in[1];
    const float* joint_valid = (const float*)d_in[2];
    float* out = (float*)d_out;
    (void)in_sizes; (void)n_in; (void)out_size;

    const int SIM_SMEM = 1024 + 3 * TILEB;   // A tile + 2 B buffers
    cudaFuncSetAttribute(sim_mma_kernel, cudaFuncAttributeMaxDynamicSharedMemorySize, SIM_SMEM);

    norm_bf16_kernel<<<(LAYERS * TWON) / 16, 256>>>(emb_i, emb_j);
    sim_mma_kernel<<<LAYERS * 32, 256, SIM_SMEM>>>();
    finalize_kernel<<<1, 256>>>(joint_valid, out);
}